// round 15
// baseline (speedup 1.0000x reference)
#include <cuda_runtime.h>
#include <cuda_fp16.h>
#include <cstdint>
#include <cstddef>

#define M_PTS 100000

// level-0 volume dims (D,H,W)
#define D0v 176
#define H0v 208
#define W0v 176
#define D1v 88
#define H1v 104
#define W1v 88
#define D2v 44
#define H2v 52
#define W2v 44

// ================= helpers =================
__device__ __forceinline__ uint32_t smem_to_u32(const void* p) {
    uint32_t a;
    asm("{ .reg .u64 t; cvta.to.shared.u64 t, %1; cvt.u32.u64 %0, t; }" : "=r"(a) : "l"(p));
    return a;
}

// fp16 2-way split with scaled low plane:
//   a ~= h0 + h1/2048,  h0 = f16(a), h1 = f16((a - h0) * 2048)   (residual ~2^-22 |a|)
__device__ __forceinline__ void split2h(float a, __half& h0, __half& h1) {
    h0 = __float2half_rn(a);
    float r = __fadd_rn(a, -__half2float(h0));
    h1 = __float2half_rn(__fmul_rn(r, 2048.0f));
}

__device__ __forceinline__ void ldm4(uint32_t addr, uint32_t& r0, uint32_t& r1, uint32_t& r2, uint32_t& r3) {
    asm volatile("ldmatrix.sync.aligned.m8n8.x4.shared.b16 {%0,%1,%2,%3}, [%4];"
                 : "=r"(r0), "=r"(r1), "=r"(r2), "=r"(r3) : "r"(addr));
}

// D = A*B + 0
__device__ __forceinline__ void mma_f16_zero(float* d, const uint32_t* a, const uint32_t* b) {
    asm volatile(
        "mma.sync.aligned.m16n8k16.row.col.f32.f16.f16.f32 "
        "{%0,%1,%2,%3}, {%4,%5,%6,%7}, {%8,%9}, {%10,%10,%10,%10};\n"
        : "=f"(d[0]), "=f"(d[1]), "=f"(d[2]), "=f"(d[3])
        : "r"(a[0]), "r"(a[1]), "r"(a[2]), "r"(a[3]), "r"(b[0]), "r"(b[1]), "f"(0.0f));
}
// D += A*B
__device__ __forceinline__ void mma_f16_acc(float* d, const uint32_t* a, const uint32_t* b) {
    asm volatile(
        "mma.sync.aligned.m16n8k16.row.col.f32.f16.f16.f32 "
        "{%0,%1,%2,%3}, {%4,%5,%6,%7}, {%8,%9}, {%0,%1,%2,%3};\n"
        : "+f"(d[0]), "+f"(d[1]), "+f"(d[2]), "+f"(d[3])
        : "r"(a[0]), "r"(a[1]), "r"(a[2]), "r"(a[3]), "r"(b[0]), "r"(b[1]));
}

// cp.async 16B (sm_80+ baseline; LDGSTS in SASS). src_size=0 -> zero-fill, no read.
__device__ __forceinline__ void cpa16(uint32_t saddr, const void* gptr, bool valid) {
    int sz = valid ? 16 : 0;
    asm volatile("cp.async.cg.shared.global [%0], [%1], 16, %2;"
                 :: "r"(saddr), "l"(gptr), "r"(sz));
}
#define CP_COMMIT() asm volatile("cp.async.commit_group;" ::: "memory")
#define CP_WAIT1()  asm volatile("cp.async.wait_group 1;" ::: "memory")
#define CP_WAIT0()  asm volatile("cp.async.wait_group 0;" ::: "memory")

// ================= static device scratch =================
__device__ float g_vol1[D1v * H1v * W1v];
__device__ float g_vol2[D2v * H2v * W2v];
// activation split planes (fp16, low plane pre-scaled x2048)
__device__ __half g_va[(size_t)M_PTS * 384], g_vb[(size_t)M_PTS * 384];
__device__ __half g_zla[(size_t)M_PTS * 128], g_zlb[(size_t)M_PTS * 128];
__device__ __half g_z1a[(size_t)M_PTS * 256], g_z1b[(size_t)M_PTS * 256];
__device__ __half g_z2a[(size_t)M_PTS * 512], g_z2b[(size_t)M_PTS * 512];
__device__ float g_z3[(size_t)M_PTS * 256];
// weight split planes (fp16), [n][k] k-major (native layout — no transpose needed)
__device__ __half g_wca[128 * 384], g_wcb[128 * 384];
__device__ __half g_wla[128 * 128], g_wlb[128 * 128];
__device__ __half g_w2a[512 * 256], g_w2b[512 * 256];
__device__ __half g_w3a[256 * 512], g_w3b[256 * 512];

// ================= setup kernels =================
__global__ void pool1_kernel(const float* __restrict__ V) {
    int n = blockIdx.x * blockDim.x + threadIdx.x;
    if (n >= D1v * H1v * W1v) return;
    int xx = n % W1v; int t = n / W1v; int yy = t % H1v; int zz = t / H1v;
    float s = 0.f;
#pragma unroll
    for (int dz = 0; dz < 2; dz++)
#pragma unroll
        for (int dy = 0; dy < 2; dy++)
#pragma unroll
            for (int dx = 0; dx < 2; dx++)
                s = __fadd_rn(s, V[((size_t)(2 * zz + dz) * H0v + (2 * yy + dy)) * W0v + (2 * xx + dx)]);
    g_vol1[n] = __fmul_rn(s, 0.125f);
}

__global__ void pool2_kernel() {
    int n = blockIdx.x * blockDim.x + threadIdx.x;
    if (n >= D2v * H2v * W2v) return;
    int xx = n % W2v; int t = n / W2v; int yy = t % H2v; int zz = t / H2v;
    float s = 0.f;
#pragma unroll
    for (int dz = 0; dz < 2; dz++)
#pragma unroll
        for (int dy = 0; dy < 2; dy++)
#pragma unroll
            for (int dx = 0; dx < 2; dx++)
                s = __fadd_rn(s, g_vol1[((size_t)(2 * zz + dz) * H1v + (2 * yy + dy)) * W1v + (2 * xx + dx)]);
    g_vol2[n] = __fmul_rn(s, 0.125f);
}

// split weight matrix [rows][srcK] into 2 fp16 planes [rows][dstK] (zero-padded)
__global__ void prep_split(const float* __restrict__ src,
                           __half* __restrict__ d0, __half* __restrict__ d1,
                           int rows, int srcK, int dstK) {
    int idx = blockIdx.x * blockDim.x + threadIdx.x;
    if (idx >= rows * dstK) return;
    int r = idx / dstK, k = idx - r * dstK;
    float a = (k < srcK) ? src[r * srcK + k] : 0.f;
    __half h0, h1;
    split2h(a, h0, h1);
    d0[idx] = h0; d1[idx] = h1;
}

// ================= sampling kernel (math UNCHANGED — matches reference bitwise) =================
__global__ void sample_kernel(const float* __restrict__ x, const float* __restrict__ V,
                              const float* __restrict__ fc1_w, const float* __restrict__ fc1_b) {
    const int NW = 8;
    __shared__ int   s_xi0[NW][5], s_xi1[NW][5];
    __shared__ int   s_yo0[NW][5], s_yo1[NW][5];
    __shared__ int   s_zo0[NW][5], s_zo1[NW][5];
    __shared__ float s_wx[NW][5], s_wy[NW][5], s_wz[NW][5];

    int w = threadIdx.x >> 5, lane = threadIdx.x & 31;
    int m = blockIdx.x * NW + w;
    if (m >= M_PTS) return;

    float x0 = __ldg(&x[3 * m + 0]);
    float x1 = __ldg(&x[3 * m + 1]);
    float x2 = __ldg(&x[3 * m + 2]);
    const float INV_RESC = (float)(208.0 / 176.0);   // == fl32(1/fl32(176/208))

#pragma unroll
    for (int q = 0; q < 3; q++) {
        const float* vol = (q == 0) ? V : (q == 1 ? g_vol1 : g_vol2);
        int Dd = D0v >> q, Hh = H0v >> q, Ww = W0v >> q;

        if (lane < 15) {
            int a = lane / 5, j = lane % 5;
            float xc = (a == 0) ? x0 : (a == 1 ? x1 : x2);
            int dim = (a == 0) ? Ww : (a == 1 ? Hh : Dd);
            float hi = (float)(dim - 1);
            float halfhi = __fmul_rn(0.5f, hi);            // exact
            float g = -3.0f + 1.25f * (float)j;            // exact
            float shift = __fmul_rn(__fmul_rn(__fdiv_rn(g, 208.0f), 2.0f), (float)(1 << q));
            float xq = __fadd_rn(xc, shift);
            float coords = (a == 1) ? xq : __fmul_rn(xq, INV_RESC);  // XLA reciprocal-mul
            float pix = __fmul_rn(__fadd_rn(coords, 1.0f), halfhi);
            pix = fminf(fmaxf(pix, 0.0f), hi);
            float p0f = floorf(pix);
            int i0 = (int)p0f;
            float fr = __fadd_rn(pix, -p0f);
            int i1 = min(i0 + 1, dim - 1);
            if (a == 0)      { s_xi0[w][j] = i0;           s_xi1[w][j] = i1;           s_wx[w][j] = fr; }
            else if (a == 1) { s_yo0[w][j] = i0 * Ww;      s_yo1[w][j] = i1 * Ww;      s_wy[w][j] = fr; }
            else             { s_zo0[w][j] = i0 * Ww * Hh; s_zo1[w][j] = i1 * Ww * Hh; s_wz[w][j] = fr; }
        }
        __syncwarp();

        size_t vbase = (size_t)m * 384 + q * 125;
        for (int s = lane; s < 125; s += 32) {
            int p0 = s / 25, rr = s % 25, p1 = rr / 5, p2 = rr % 5;
            int ix0 = s_xi0[w][p0], ix1 = s_xi1[w][p0];
            float fx = s_wx[w][p0];
            int yo0 = s_yo0[w][p1], yo1 = s_yo1[w][p1];
            float fy = s_wy[w][p1];
            int zo0 = s_zo0[w][p2], zo1 = s_zo1[w][p2];
            float fz = s_wz[w][p2];
            float ox = __fadd_rn(1.0f, -fx);
            float oy = __fadd_rn(1.0f, -fy);
            float oz = __fadd_rn(1.0f, -fz);
            int b00 = zo0 + yo0, b10 = zo0 + yo1, b01 = zo1 + yo0, b11 = zo1 + yo1;
            float v000 = __ldg(vol + b00 + ix0), v100 = __ldg(vol + b00 + ix1);
            float v010 = __ldg(vol + b10 + ix0), v110 = __ldg(vol + b10 + ix1);
            float v001 = __ldg(vol + b01 + ix0), v101 = __ldg(vol + b01 + ix1);
            float v011 = __ldg(vol + b11 + ix0), v111 = __ldg(vol + b11 + ix1);
            float c00 = __fadd_rn(__fmul_rn(v000, ox), __fmul_rn(v100, fx));
            float c10 = __fadd_rn(__fmul_rn(v010, ox), __fmul_rn(v110, fx));
            float c01 = __fadd_rn(__fmul_rn(v001, ox), __fmul_rn(v101, fx));
            float c11 = __fadd_rn(__fmul_rn(v011, ox), __fmul_rn(v111, fx));
            float c0 = __fadd_rn(__fmul_rn(c00, oy), __fmul_rn(c10, fy));
            float c1 = __fadd_rn(__fmul_rn(c01, oy), __fmul_rn(c11, fy));
            float val = __fadd_rn(__fmul_rn(c0, oz), __fmul_rn(c1, fz));
            __half h0, h1;
            split2h(val, h0, h1);
            g_va[vbase + s] = h0; g_vb[vbase + s] = h1;
        }
        __syncwarp();
    }
    if (lane < 9) {
        size_t o = (size_t)m * 384 + 375 + lane;
        g_va[o] = __float2half_rn(0.f);
        g_vb[o] = __float2half_rn(0.f);
    }

    // fc1: z_point = leaky_relu(x @ fc1_w^T + fc1_b)  (unchanged math, split output)
#pragma unroll
    for (int r = 0; r < 4; r++) {
        int o = lane + r * 32;
        float d = __fmul_rn(fc1_w[o * 3 + 0], x0);
        d = fmaf(fc1_w[o * 3 + 1], x1, d);
        d = fmaf(fc1_w[o * 3 + 2], x2, d);
        float z = __fadd_rn(d, fc1_b[o]);
        z = (z >= 0.f) ? z : __fmul_rn(0.2f, z);
        __half h0, h1;
        split2h(z, h0, h1);
        size_t zo = (size_t)m * 256 + o;
        g_z1a[zo] = h0; g_z1b[zo] = h1;
    }
}

// ================= emulated-fp32 GEMM: fp16 3-term split, cp.async double buffer =================
// C[M x N] = A[M x K] @ B^T + bias. A planes [M][lda], B planes [N][ldb] (k-major).
// Terms: hh + (h*l + l*h) * 2^-11; TC accumulators chained across a 32-K chunk,
// flushed to fp32 RN master per chunk. CTA tile 128x128, 8 warps (4x2), warp 32x64.
#define RS 80            // padded smem row stride (32 fp16 + 16B pad) — conflict-free ldmatrix
#define PLANE 10240      // 128 * RS
#define BOFF 20480       // 2 * PLANE (B planes start)
#define HALFBUF 40960    // one stage: A0,A1,B0,B1 planes
#define MG_SMEM 81920    // two stages

template <bool LEAKY, bool SPLITOUT>
__global__ __launch_bounds__(256, 2) void mgemm(
    const __half* __restrict__ A0, const __half* __restrict__ A1,
    const __half* __restrict__ B0, const __half* __restrict__ B1,
    float* __restrict__ Cf,
    __half* __restrict__ C0, __half* __restrict__ C1,
    const float* __restrict__ bias, int M, int K, int lda, int ldb, int ldc) {
    extern __shared__ char smc[];
    uint32_t sb = smem_to_u32(smc);
    int tid = threadIdx.x, lane = tid & 31, wid = tid >> 5;
    int wm = wid & 3, wn = wid >> 2;
    int row0 = blockIdx.x * 128;
    int col0 = blockIdx.y * 128;

    float c[2][8][4];   // master fp32 accumulators
#pragma unroll
    for (int i = 0; i < 2; i++)
#pragma unroll
        for (int j = 0; j < 8; j++)
#pragma unroll
            for (int k = 0; k < 4; k++) c[i][j][k] = 0.f;

    int lrow = tid >> 2, lseg = tid & 3;
    int ti = lane >> 3, rr = lane & 7;
    const float LOWSC = 1.0f / 2048.0f;

    const int nch = K >> 5;

    // ---- async stage of one 32-K chunk into buffer bp ----
    auto stage = [&](int kc, int bp) {
        uint32_t bufo = sb + (uint32_t)bp * HALFBUF;
#pragma unroll
        for (int u = 0; u < 2; u++) {
            int row = lrow + u * 64;
            int gr = row0 + row;
            bool av = (gr < M);
            uint32_t so = bufo + (uint32_t)(row * RS + lseg * 16);
            size_t ga = av ? ((size_t)gr * lda + kc + lseg * 8) : 0;
            cpa16(so, A0 + ga, av);
            cpa16(so + PLANE, A1 + ga, av);
            size_t gb = (size_t)(col0 + row) * ldb + kc + lseg * 8;
            cpa16(so + BOFF, B0 + gb, true);
            cpa16(so + BOFF + PLANE, B1 + gb, true);
        }
    };

    stage(0, 0);
    CP_COMMIT();

    for (int ic = 0; ic < nch; ic++) {
        uint32_t bo = (uint32_t)(ic & 1) * HALFBUF;
        if (ic + 1 < nch) {
            stage((ic + 1) << 5, (ic & 1) ^ 1);
            CP_COMMIT();
            CP_WAIT1();
        } else {
            CP_WAIT0();
        }
        __syncthreads();

        // ---- compute chunk from buffer bo: jp-outer, kk-chained TC accumulators ----
#pragma unroll
        for (int jp = 0; jp < 4; jp++) {
            float dhh[2][2][4], dlo[2][2][4];   // [half][mi][4]
#pragma unroll
            for (int kk = 0; kk < 2; kk++) {
                uint32_t ah[2][4], al[2][4];
#pragma unroll
                for (int mi = 0; mi < 2; mi++) {
                    uint32_t abase = sb + bo +
                        (uint32_t)((wm * 32 + mi * 16 + rr + (ti & 1) * 8) * RS + (ti >> 1) * 16 + kk * 32);
                    ldm4(abase, ah[mi][0], ah[mi][1], ah[mi][2], ah[mi][3]);
                    ldm4(abase + PLANE, al[mi][0], al[mi][1], al[mi][2], al[mi][3]);
                }
                uint32_t bbase = sb + bo + BOFF +
                    (uint32_t)((wn * 64 + (jp * 2 + (ti >> 1)) * 8 + rr) * RS + (ti & 1) * 16 + kk * 32);
                uint32_t bh[2][2], bl[2][2];
                ldm4(bbase, bh[0][0], bh[0][1], bh[1][0], bh[1][1]);
                ldm4(bbase + PLANE, bl[0][0], bl[0][1], bl[1][0], bl[1][1]);
#pragma unroll
                for (int half = 0; half < 2; half++)
#pragma unroll
                    for (int mi = 0; mi < 2; mi++) {
                        if (kk == 0) {
                            mma_f16_zero(dhh[half][mi], ah[mi], bh[half]);
                            mma_f16_zero(dlo[half][mi], ah[mi], bl[half]);
                        } else {
                            mma_f16_acc(dhh[half][mi], ah[mi], bh[half]);
                            mma_f16_acc(dlo[half][mi], ah[mi], bl[half]);
                        }
                        mma_f16_acc(dlo[half][mi], al[mi], bh[half]);
                    }
            }
            // flush chunk into fp32 master
#pragma unroll
            for (int half = 0; half < 2; half++) {
                int nj = jp * 2 + half;
#pragma unroll
                for (int mi = 0; mi < 2; mi++)
#pragma unroll
                    for (int r = 0; r < 4; r++) {
                        float t = __fadd_rn(c[mi][nj][r], dhh[half][mi][r]);
                        c[mi][nj][r] = fmaf(dlo[half][mi][r], LOWSC, t);
                    }
            }
        }
        __syncthreads();
    }

    // ---- epilogue ----
    int g = lane >> 2, i2 = (lane & 3) * 2;
#pragma unroll
    for (int mi = 0; mi < 2; mi++) {
#pragma unroll
        for (int half = 0; half < 2; half++) {
            int gr = row0 + wm * 32 + mi * 16 + g + half * 8;
            if (gr >= M) continue;
#pragma unroll
            for (int nj = 0; nj < 8; nj++) {
                int gc = col0 + wn * 64 + nj * 8 + i2;
                float v0 = __fadd_rn(c[mi][nj][half * 2 + 0], __ldg(&bias[gc]));
                float v1 = __fadd_rn(c[mi][nj][half * 2 + 1], __ldg(&bias[gc + 1]));
                if (LEAKY) {
                    v0 = (v0 >= 0.f) ? v0 : __fmul_rn(0.2f, v0);
                    v1 = (v1 >= 0.f) ? v1 : __fmul_rn(0.2f, v1);
                }
                size_t off = (size_t)gr * ldc + gc;
                if (SPLITOUT) {
                    __half h0, h1, j0, j1;
                    split2h(v0, h0, h1);
                    split2h(v1, j0, j1);
                    *reinterpret_cast<__half2*>(C0 + off) = __halves2half2(h0, j0);
                    *reinterpret_cast<__half2*>(C1 + off) = __halves2half2(h1, j1);
                } else {
                    *reinterpret_cast<float2*>(Cf + off) = make_float2(v0, v1);
                }
            }
        }
    }
}

// ================= fc4 + ODE update (UNCHANGED) =================
__global__ void fc4_kernel(const float* __restrict__ xin, float* __restrict__ xout,
                           const float* __restrict__ w4, const float* __restrict__ b4) {
    int m = blockIdx.x * blockDim.x + threadIdx.x;
    if (m >= M_PTS) return;
    const float* z = &g_z3[(size_t)m * 256];
    float s0 = 0.f, s1 = 0.f, s2 = 0.f;
    for (int k = 0; k < 256; k++) {
        float zv = z[k];
        s0 = fmaf(zv, __ldg(&w4[k]), s0);
        s1 = fmaf(zv, __ldg(&w4[256 + k]), s1);
        s2 = fmaf(zv, __ldg(&w4[512 + k]), s2);
    }
    float d0 = __fadd_rn(s0, b4[0]);
    float d1 = __fadd_rn(s1, b4[1]);
    float d2 = __fadd_rn(s2, b4[2]);
    xout[3 * m + 0] = __fadd_rn(xin[3 * m + 0], __fmul_rn(0.2f, d0));
    xout[3 * m + 1] = __fadd_rn(xin[3 * m + 1], __fmul_rn(0.2f, d1));
    xout[3 * m + 2] = __fadd_rn(xin[3 * m + 2], __fmul_rn(0.2f, d2));
}

// ================= launch =================
extern "C" void kernel_launch(void* const* d_in, const int* in_sizes, int n_in,
                              void* d_out, int out_size) {
    const float* x_in  = (const float*)d_in[0];
    const float* V     = (const float*)d_in[1];
    const float* fc1_w = (const float*)d_in[2];
    const float* fc1_b = (const float*)d_in[3];
    const float* fc2_w = (const float*)d_in[4];
    const float* fc2_b = (const float*)d_in[5];
    const float* fc3_w = (const float*)d_in[6];
    const float* fc3_b = (const float*)d_in[7];
    const float* fc4_w = (const float*)d_in[8];
    const float* fc4_b = (const float*)d_in[9];
    const float* conv_w = (const float*)d_in[10];
    const float* conv_b = (const float*)d_in[11];
    const float* lfc_w  = (const float*)d_in[12];
    const float* lfc_b  = (const float*)d_in[13];
    float* xbuf = (float*)d_out;

    __half *va, *vb, *zla, *zlb, *z1a, *z1b, *z2a, *z2b;
    __half *wca, *wcb, *wla, *wlb, *w2a, *w2b, *w3a, *w3b;
    float* z3;
    cudaGetSymbolAddress((void**)&va, g_va);   cudaGetSymbolAddress((void**)&vb, g_vb);
    cudaGetSymbolAddress((void**)&zla, g_zla); cudaGetSymbolAddress((void**)&zlb, g_zlb);
    cudaGetSymbolAddress((void**)&z1a, g_z1a); cudaGetSymbolAddress((void**)&z1b, g_z1b);
    cudaGetSymbolAddress((void**)&z2a, g_z2a); cudaGetSymbolAddress((void**)&z2b, g_z2b);
    cudaGetSymbolAddress((void**)&wca, g_wca); cudaGetSymbolAddress((void**)&wcb, g_wcb);
    cudaGetSymbolAddress((void**)&wla, g_wla); cudaGetSymbolAddress((void**)&wlb, g_wlb);
    cudaGetSymbolAddress((void**)&w2a, g_w2a); cudaGetSymbolAddress((void**)&w2b, g_w2b);
    cudaGetSymbolAddress((void**)&w3a, g_w3a); cudaGetSymbolAddress((void**)&w3b, g_w3b);
    cudaGetSymbolAddress((void**)&z3, g_z3);

    cudaFuncSetAttribute(mgemm<false, true>, cudaFuncAttributeMaxDynamicSharedMemorySize, MG_SMEM);
    cudaFuncSetAttribute(mgemm<true, true>,  cudaFuncAttributeMaxDynamicSharedMemorySize, MG_SMEM);
    cudaFuncSetAttribute(mgemm<true, false>, cudaFuncAttributeMaxDynamicSharedMemorySize, MG_SMEM);

    // setup (cheap, deterministic, in-graph)
    pool1_kernel<<<(D1v * H1v * W1v + 255) / 256, 256>>>(V);
    pool2_kernel<<<(D2v * H2v * W2v + 255) / 256, 256>>>();
    prep_split<<<(128 * 384 + 255) / 256, 256>>>(conv_w, wca, wcb, 128, 375, 384);
    prep_split<<<(128 * 128 + 255) / 256, 256>>>(lfc_w, wla, wlb, 128, 128, 128);
    prep_split<<<(512 * 256 + 255) / 256, 256>>>(fc2_w, w2a, w2b, 512, 256, 256);
    prep_split<<<(256 * 512 + 255) / 256, 256>>>(fc3_w, w3a, w3b, 256, 512, 512);

    const int MB = (M_PTS + 127) / 128;   // 782
    for (int step = 0; step < 5; step++) {
        const float* xcur = (step == 0) ? x_in : xbuf;
        sample_kernel<<<(M_PTS + 7) / 8, 256>>>(xcur, V, fc1_w, fc1_b);
        // zl = v @ conv_w^T + conv_b  (N=128)
        mgemm<false, true><<<dim3(MB, 1), 256, MG_SMEM>>>(
            va, vb, wca, wcb, nullptr, zla, zlb, conv_b, M_PTS, 384, 384, 384, 128);
        // z_local = zl @ lfc_w^T + lfc_b  -> z1 cols [128,256)
        mgemm<false, true><<<dim3(MB, 1), 256, MG_SMEM>>>(
            zla, zlb, wla, wlb, nullptr, z1a + 128, z1b + 128, lfc_b, M_PTS, 128, 128, 128, 256);
        // z2 = leaky(z1 @ fc2_w^T + b2)  (N=512)
        mgemm<true, true><<<dim3(MB, 4), 256, MG_SMEM>>>(
            z1a, z1b, w2a, w2b, nullptr, z2a, z2b, fc2_b, M_PTS, 256, 256, 256, 512);
        // z3 = leaky(z2 @ fc3_w^T + b3)  (N=256, fp32 out)
        mgemm<true, false><<<dim3(MB, 2), 256, MG_SMEM>>>(
            z2a, z2b, w3a, w3b, z3, nullptr, nullptr, fc3_b, M_PTS, 512, 512, 512, 256);
        // x += 0.2 * (z3 @ w4^T + b4)
        fc4_kernel<<<(M_PTS + 255) / 256, 256>>>(xcur, xbuf, fc4_w, fc4_b);
    }
}

// round 16
// speedup vs baseline: 1.1183x; 1.1183x over previous
#include <cuda_runtime.h>
#include <cuda_fp16.h>
#include <cstdint>
#include <cstddef>

#define M_PTS 100000

// level-0 volume dims (D,H,W)
#define D0v 176
#define H0v 208
#define W0v 176
#define D1v 88
#define H1v 104
#define W1v 88
#define D2v 44
#define H2v 52
#define W2v 44

// ================= helpers =================
__device__ __forceinline__ uint32_t smem_to_u32(const void* p) {
    uint32_t a;
    asm("{ .reg .u64 t; cvta.to.shared.u64 t, %1; cvt.u32.u64 %0, t; }" : "=r"(a) : "l"(p));
    return a;
}

// fp16 2-way split with scaled low plane:
//   a ~= h0 + h1/2048,  h0 = f16(a), h1 = f16((a - h0) * 2048)   (residual ~2^-22 |a|)
__device__ __forceinline__ void split2h(float a, __half& h0, __half& h1) {
    h0 = __float2half_rn(a);
    float r = __fadd_rn(a, -__half2float(h0));
    h1 = __float2half_rn(__fmul_rn(r, 2048.0f));
}

__device__ __forceinline__ void ldm4(uint32_t addr, uint32_t& r0, uint32_t& r1, uint32_t& r2, uint32_t& r3) {
    asm volatile("ldmatrix.sync.aligned.m8n8.x4.shared.b16 {%0,%1,%2,%3}, [%4];"
                 : "=r"(r0), "=r"(r1), "=r"(r2), "=r"(r3) : "r"(addr));
}

// D = A*B + 0
__device__ __forceinline__ void mma_f16_zero(float* d, const uint32_t* a, const uint32_t* b) {
    asm volatile(
        "mma.sync.aligned.m16n8k16.row.col.f32.f16.f16.f32 "
        "{%0,%1,%2,%3}, {%4,%5,%6,%7}, {%8,%9}, {%10,%10,%10,%10};\n"
        : "=f"(d[0]), "=f"(d[1]), "=f"(d[2]), "=f"(d[3])
        : "r"(a[0]), "r"(a[1]), "r"(a[2]), "r"(a[3]), "r"(b[0]), "r"(b[1]), "f"(0.0f));
}
// D += A*B
__device__ __forceinline__ void mma_f16_acc(float* d, const uint32_t* a, const uint32_t* b) {
    asm volatile(
        "mma.sync.aligned.m16n8k16.row.col.f32.f16.f16.f32 "
        "{%0,%1,%2,%3}, {%4,%5,%6,%7}, {%8,%9}, {%0,%1,%2,%3};\n"
        : "+f"(d[0]), "+f"(d[1]), "+f"(d[2]), "+f"(d[3])
        : "r"(a[0]), "r"(a[1]), "r"(a[2]), "r"(a[3]), "r"(b[0]), "r"(b[1]));
}

// cp.async 16B (sm_80+ baseline; LDGSTS in SASS). src_size=0 -> zero-fill, no read.
__device__ __forceinline__ void cpa16(uint32_t saddr, const void* gptr, bool valid) {
    int sz = valid ? 16 : 0;
    asm volatile("cp.async.cg.shared.global [%0], [%1], 16, %2;"
                 :: "r"(saddr), "l"(gptr), "r"(sz));
}
#define CP_COMMIT() asm volatile("cp.async.commit_group;" ::: "memory")
#define CP_WAIT1()  asm volatile("cp.async.wait_group 1;" ::: "memory")
#define CP_WAIT0()  asm volatile("cp.async.wait_group 0;" ::: "memory")

// ================= static device scratch =================
__device__ float g_vol1[D1v * H1v * W1v];
__device__ float g_vol2[D2v * H2v * W2v];
// activation split planes (fp16, low plane pre-scaled x2048)
__device__ __half g_va[(size_t)M_PTS * 384], g_vb[(size_t)M_PTS * 384];
__device__ __half g_zla[(size_t)M_PTS * 128], g_zlb[(size_t)M_PTS * 128];
__device__ __half g_z1a[(size_t)M_PTS * 256], g_z1b[(size_t)M_PTS * 256];
__device__ __half g_z2a[(size_t)M_PTS * 512], g_z2b[(size_t)M_PTS * 512];
__device__ float g_z3[(size_t)M_PTS * 256];
// weight split planes (fp16), [n][k] k-major (native layout — no transpose needed)
__device__ __half g_wca[128 * 384], g_wcb[128 * 384];
__device__ __half g_wla[128 * 128], g_wlb[128 * 128];
__device__ __half g_w2a[512 * 256], g_w2b[512 * 256];
__device__ __half g_w3a[256 * 512], g_w3b[256 * 512];

// ================= setup kernels =================
__global__ void pool1_kernel(const float* __restrict__ V) {
    int n = blockIdx.x * blockDim.x + threadIdx.x;
    if (n >= D1v * H1v * W1v) return;
    int xx = n % W1v; int t = n / W1v; int yy = t % H1v; int zz = t / H1v;
    float s = 0.f;
#pragma unroll
    for (int dz = 0; dz < 2; dz++)
#pragma unroll
        for (int dy = 0; dy < 2; dy++)
#pragma unroll
            for (int dx = 0; dx < 2; dx++)
                s = __fadd_rn(s, V[((size_t)(2 * zz + dz) * H0v + (2 * yy + dy)) * W0v + (2 * xx + dx)]);
    g_vol1[n] = __fmul_rn(s, 0.125f);
}

__global__ void pool2_kernel() {
    int n = blockIdx.x * blockDim.x + threadIdx.x;
    if (n >= D2v * H2v * W2v) return;
    int xx = n % W2v; int t = n / W2v; int yy = t % H2v; int zz = t / H2v;
    float s = 0.f;
#pragma unroll
    for (int dz = 0; dz < 2; dz++)
#pragma unroll
        for (int dy = 0; dy < 2; dy++)
#pragma unroll
            for (int dx = 0; dx < 2; dx++)
                s = __fadd_rn(s, g_vol1[((size_t)(2 * zz + dz) * H1v + (2 * yy + dy)) * W1v + (2 * xx + dx)]);
    g_vol2[n] = __fmul_rn(s, 0.125f);
}

// split weight matrix [rows][srcK] into 2 fp16 planes [rows][dstK] (zero-padded)
__global__ void prep_split(const float* __restrict__ src,
                           __half* __restrict__ d0, __half* __restrict__ d1,
                           int rows, int srcK, int dstK) {
    int idx = blockIdx.x * blockDim.x + threadIdx.x;
    if (idx >= rows * dstK) return;
    int r = idx / dstK, k = idx - r * dstK;
    float a = (k < srcK) ? src[r * srcK + k] : 0.f;
    __half h0, h1;
    split2h(a, h0, h1);
    d0[idx] = h0; d1[idx] = h1;
}

// ================= sampling kernel (math UNCHANGED — matches reference bitwise) =================
__global__ void sample_kernel(const float* __restrict__ x, const float* __restrict__ V,
                              const float* __restrict__ fc1_w, const float* __restrict__ fc1_b) {
    const int NW = 8;
    __shared__ int   s_xi0[NW][5], s_xi1[NW][5];
    __shared__ int   s_yo0[NW][5], s_yo1[NW][5];
    __shared__ int   s_zo0[NW][5], s_zo1[NW][5];
    __shared__ float s_wx[NW][5], s_wy[NW][5], s_wz[NW][5];

    int w = threadIdx.x >> 5, lane = threadIdx.x & 31;
    int m = blockIdx.x * NW + w;
    if (m >= M_PTS) return;

    float x0 = __ldg(&x[3 * m + 0]);
    float x1 = __ldg(&x[3 * m + 1]);
    float x2 = __ldg(&x[3 * m + 2]);
    const float INV_RESC = (float)(208.0 / 176.0);   // == fl32(1/fl32(176/208))

#pragma unroll
    for (int q = 0; q < 3; q++) {
        const float* vol = (q == 0) ? V : (q == 1 ? g_vol1 : g_vol2);
        int Dd = D0v >> q, Hh = H0v >> q, Ww = W0v >> q;

        if (lane < 15) {
            int a = lane / 5, j = lane % 5;
            float xc = (a == 0) ? x0 : (a == 1 ? x1 : x2);
            int dim = (a == 0) ? Ww : (a == 1 ? Hh : Dd);
            float hi = (float)(dim - 1);
            float halfhi = __fmul_rn(0.5f, hi);            // exact
            float g = -3.0f + 1.25f * (float)j;            // exact
            float shift = __fmul_rn(__fmul_rn(__fdiv_rn(g, 208.0f), 2.0f), (float)(1 << q));
            float xq = __fadd_rn(xc, shift);
            float coords = (a == 1) ? xq : __fmul_rn(xq, INV_RESC);  // XLA reciprocal-mul
            float pix = __fmul_rn(__fadd_rn(coords, 1.0f), halfhi);
            pix = fminf(fmaxf(pix, 0.0f), hi);
            float p0f = floorf(pix);
            int i0 = (int)p0f;
            float fr = __fadd_rn(pix, -p0f);
            int i1 = min(i0 + 1, dim - 1);
            if (a == 0)      { s_xi0[w][j] = i0;           s_xi1[w][j] = i1;           s_wx[w][j] = fr; }
            else if (a == 1) { s_yo0[w][j] = i0 * Ww;      s_yo1[w][j] = i1 * Ww;      s_wy[w][j] = fr; }
            else             { s_zo0[w][j] = i0 * Ww * Hh; s_zo1[w][j] = i1 * Ww * Hh; s_wz[w][j] = fr; }
        }
        __syncwarp();

        size_t vbase = (size_t)m * 384 + q * 125;
        for (int s = lane; s < 125; s += 32) {
            int p0 = s / 25, rr = s % 25, p1 = rr / 5, p2 = rr % 5;
            int ix0 = s_xi0[w][p0], ix1 = s_xi1[w][p0];
            float fx = s_wx[w][p0];
            int yo0 = s_yo0[w][p1], yo1 = s_yo1[w][p1];
            float fy = s_wy[w][p1];
            int zo0 = s_zo0[w][p2], zo1 = s_zo1[w][p2];
            float fz = s_wz[w][p2];
            float ox = __fadd_rn(1.0f, -fx);
            float oy = __fadd_rn(1.0f, -fy);
            float oz = __fadd_rn(1.0f, -fz);
            int b00 = zo0 + yo0, b10 = zo0 + yo1, b01 = zo1 + yo0, b11 = zo1 + yo1;
            float v000 = __ldg(vol + b00 + ix0), v100 = __ldg(vol + b00 + ix1);
            float v010 = __ldg(vol + b10 + ix0), v110 = __ldg(vol + b10 + ix1);
            float v001 = __ldg(vol + b01 + ix0), v101 = __ldg(vol + b01 + ix1);
            float v011 = __ldg(vol + b11 + ix0), v111 = __ldg(vol + b11 + ix1);
            float c00 = __fadd_rn(__fmul_rn(v000, ox), __fmul_rn(v100, fx));
            float c10 = __fadd_rn(__fmul_rn(v010, ox), __fmul_rn(v110, fx));
            float c01 = __fadd_rn(__fmul_rn(v001, ox), __fmul_rn(v101, fx));
            float c11 = __fadd_rn(__fmul_rn(v011, ox), __fmul_rn(v111, fx));
            float c0 = __fadd_rn(__fmul_rn(c00, oy), __fmul_rn(c10, fy));
            float c1 = __fadd_rn(__fmul_rn(c01, oy), __fmul_rn(c11, fy));
            float val = __fadd_rn(__fmul_rn(c0, oz), __fmul_rn(c1, fz));
            __half h0, h1;
            split2h(val, h0, h1);
            g_va[vbase + s] = h0; g_vb[vbase + s] = h1;
        }
        __syncwarp();
    }
    if (lane < 9) {
        size_t o = (size_t)m * 384 + 375 + lane;
        g_va[o] = __float2half_rn(0.f);
        g_vb[o] = __float2half_rn(0.f);
    }

    // fc1: z_point = leaky_relu(x @ fc1_w^T + fc1_b)  (unchanged math, split output)
#pragma unroll
    for (int r = 0; r < 4; r++) {
        int o = lane + r * 32;
        float d = __fmul_rn(fc1_w[o * 3 + 0], x0);
        d = fmaf(fc1_w[o * 3 + 1], x1, d);
        d = fmaf(fc1_w[o * 3 + 2], x2, d);
        float z = __fadd_rn(d, fc1_b[o]);
        z = (z >= 0.f) ? z : __fmul_rn(0.2f, z);
        __half h0, h1;
        split2h(z, h0, h1);
        size_t zo = (size_t)m * 256 + o;
        g_z1a[zo] = h0; g_z1b[zo] = h1;
    }
}

// ================= emulated-fp32 GEMM: fp16 3-term split, cp.async double buffer =================
// Compute loop identical to the round-14 (6866us) kernel: kk-outer, jp-inner,
// TRANSIENT dhh[4]/dlo[4] flushed to fp32 master per k16 — low register pressure.
// Only the load path changed: synchronous float4 loads -> cp.async double buffer.
#define RS 80            // padded smem row stride (32 fp16 + 16B pad) — conflict-free ldmatrix
#define PLANE 10240      // 128 * RS
#define BOFF 20480       // 2 * PLANE (B planes start)
#define HALFBUF 40960    // one stage: A0,A1,B0,B1 planes
#define MG_SMEM 81920    // two stages

template <bool LEAKY, bool SPLITOUT>
__global__ __launch_bounds__(256, 2) void mgemm(
    const __half* __restrict__ A0, const __half* __restrict__ A1,
    const __half* __restrict__ B0, const __half* __restrict__ B1,
    float* __restrict__ Cf,
    __half* __restrict__ C0, __half* __restrict__ C1,
    const float* __restrict__ bias, int M, int K, int lda, int ldb, int ldc) {
    extern __shared__ char smc[];
    uint32_t sb = smem_to_u32(smc);
    int tid = threadIdx.x, lane = tid & 31, wid = tid >> 5;
    int wm = wid & 3, wn = wid >> 2;
    int row0 = blockIdx.x * 128;
    int col0 = blockIdx.y * 128;

    float c[2][8][4];   // master fp32 accumulators
#pragma unroll
    for (int i = 0; i < 2; i++)
#pragma unroll
        for (int j = 0; j < 8; j++)
#pragma unroll
            for (int k = 0; k < 4; k++) c[i][j][k] = 0.f;

    int lrow = tid >> 2, lseg = tid & 3;
    int ti = lane >> 3, rr = lane & 7;
    const float LOWSC = 1.0f / 2048.0f;

    const int nch = K >> 5;

    // ---- async stage of one 32-K chunk into buffer bp ----
    auto stage = [&](int kc, int bp) {
        uint32_t bufo = sb + (uint32_t)bp * HALFBUF;
#pragma unroll
        for (int u = 0; u < 2; u++) {
            int row = lrow + u * 64;
            int gr = row0 + row;
            bool av = (gr < M);
            uint32_t so = bufo + (uint32_t)(row * RS + lseg * 16);
            size_t ga = av ? ((size_t)gr * lda + kc + lseg * 8) : 0;
            cpa16(so, A0 + ga, av);
            cpa16(so + PLANE, A1 + ga, av);
            size_t gb = (size_t)(col0 + row) * ldb + kc + lseg * 8;
            cpa16(so + BOFF, B0 + gb, true);
            cpa16(so + BOFF + PLANE, B1 + gb, true);
        }
    };

    stage(0, 0);
    CP_COMMIT();

    for (int ic = 0; ic < nch; ic++) {
        uint32_t bo = (uint32_t)(ic & 1) * HALFBUF;
        if (ic + 1 < nch) {
            stage((ic + 1) << 5, (ic & 1) ^ 1);
            CP_COMMIT();
            CP_WAIT1();
        } else {
            CP_WAIT0();
        }
        __syncthreads();

        // ---- compute chunk from buffer bo (round-14 structure: per-k16 flush) ----
#pragma unroll
        for (int kk = 0; kk < 2; kk++) {
            uint32_t ah[2][4], al[2][4];
#pragma unroll
            for (int mi = 0; mi < 2; mi++) {
                uint32_t abase = sb + bo +
                    (uint32_t)((wm * 32 + mi * 16 + rr + (ti & 1) * 8) * RS + (ti >> 1) * 16 + kk * 32);
                ldm4(abase, ah[mi][0], ah[mi][1], ah[mi][2], ah[mi][3]);
                ldm4(abase + PLANE, al[mi][0], al[mi][1], al[mi][2], al[mi][3]);
            }
#pragma unroll
            for (int jp = 0; jp < 4; jp++) {
                uint32_t bbase = sb + bo + BOFF +
                    (uint32_t)((wn * 64 + (jp * 2 + (ti >> 1)) * 8 + rr) * RS + (ti & 1) * 16 + kk * 32);
                uint32_t bh[2][2], bl[2][2];
                ldm4(bbase, bh[0][0], bh[0][1], bh[1][0], bh[1][1]);
                ldm4(bbase + PLANE, bl[0][0], bl[0][1], bl[1][0], bl[1][1]);
#pragma unroll
                for (int half = 0; half < 2; half++) {
                    int nj = 2 * jp + half;
#pragma unroll
                    for (int mi = 0; mi < 2; mi++) {
                        float dhh[4], dlo[4];
                        mma_f16_zero(dhh, ah[mi], bh[half]);
                        mma_f16_zero(dlo, ah[mi], bl[half]);
                        mma_f16_acc(dlo, al[mi], bh[half]);
#pragma unroll
                        for (int r = 0; r < 4; r++) {
                            float t = __fadd_rn(c[mi][nj][r], dhh[r]);
                            c[mi][nj][r] = fmaf(dlo[r], LOWSC, t);
                        }
                    }
                }
            }
        }
        __syncthreads();
    }

    // ---- epilogue ----
    int g = lane >> 2, i2 = (lane & 3) * 2;
#pragma unroll
    for (int mi = 0; mi < 2; mi++) {
#pragma unroll
        for (int half = 0; half < 2; half++) {
            int gr = row0 + wm * 32 + mi * 16 + g + half * 8;
            if (gr >= M) continue;
#pragma unroll
            for (int nj = 0; nj < 8; nj++) {
                int gc = col0 + wn * 64 + nj * 8 + i2;
                float v0 = __fadd_rn(c[mi][nj][half * 2 + 0], __ldg(&bias[gc]));
                float v1 = __fadd_rn(c[mi][nj][half * 2 + 1], __ldg(&bias[gc + 1]));
                if (LEAKY) {
                    v0 = (v0 >= 0.f) ? v0 : __fmul_rn(0.2f, v0);
                    v1 = (v1 >= 0.f) ? v1 : __fmul_rn(0.2f, v1);
                }
                size_t off = (size_t)gr * ldc + gc;
                if (SPLITOUT) {
                    __half h0, h1, j0, j1;
                    split2h(v0, h0, h1);
                    split2h(v1, j0, j1);
                    *reinterpret_cast<__half2*>(C0 + off) = __halves2half2(h0, j0);
                    *reinterpret_cast<__half2*>(C1 + off) = __halves2half2(h1, j1);
                } else {
                    *reinterpret_cast<float2*>(Cf + off) = make_float2(v0, v1);
                }
            }
        }
    }
}

// ================= fc4 + ODE update (UNCHANGED) =================
__global__ void fc4_kernel(const float* __restrict__ xin, float* __restrict__ xout,
                           const float* __restrict__ w4, const float* __restrict__ b4) {
    int m = blockIdx.x * blockDim.x + threadIdx.x;
    if (m >= M_PTS) return;
    const float* z = &g_z3[(size_t)m * 256];
    float s0 = 0.f, s1 = 0.f, s2 = 0.f;
    for (int k = 0; k < 256; k++) {
        float zv = z[k];
        s0 = fmaf(zv, __ldg(&w4[k]), s0);
        s1 = fmaf(zv, __ldg(&w4[256 + k]), s1);
        s2 = fmaf(zv, __ldg(&w4[512 + k]), s2);
    }
    float d0 = __fadd_rn(s0, b4[0]);
    float d1 = __fadd_rn(s1, b4[1]);
    float d2 = __fadd_rn(s2, b4[2]);
    xout[3 * m + 0] = __fadd_rn(xin[3 * m + 0], __fmul_rn(0.2f, d0));
    xout[3 * m + 1] = __fadd_rn(xin[3 * m + 1], __fmul_rn(0.2f, d1));
    xout[3 * m + 2] = __fadd_rn(xin[3 * m + 2], __fmul_rn(0.2f, d2));
}

// ================= launch =================
extern "C" void kernel_launch(void* const* d_in, const int* in_sizes, int n_in,
                              void* d_out, int out_size) {
    const float* x_in  = (const float*)d_in[0];
    const float* V     = (const float*)d_in[1];
    const float* fc1_w = (const float*)d_in[2];
    const float* fc1_b = (const float*)d_in[3];
    const float* fc2_w = (const float*)d_in[4];
    const float* fc2_b = (const float*)d_in[5];
    const float* fc3_w = (const float*)d_in[6];
    const float* fc3_b = (const float*)d_in[7];
    const float* fc4_w = (const float*)d_in[8];
    const float* fc4_b = (const float*)d_in[9];
    const float* conv_w = (const float*)d_in[10];
    const float* conv_b = (const float*)d_in[11];
    const float* lfc_w  = (const float*)d_in[12];
    const float* lfc_b  = (const float*)d_in[13];
    float* xbuf = (float*)d_out;

    __half *va, *vb, *zla, *zlb, *z1a, *z1b, *z2a, *z2b;
    __half *wca, *wcb, *wla, *wlb, *w2a, *w2b, *w3a, *w3b;
    float* z3;
    cudaGetSymbolAddress((void**)&va, g_va);   cudaGetSymbolAddress((void**)&vb, g_vb);
    cudaGetSymbolAddress((void**)&zla, g_zla); cudaGetSymbolAddress((void**)&zlb, g_zlb);
    cudaGetSymbolAddress((void**)&z1a, g_z1a); cudaGetSymbolAddress((void**)&z1b, g_z1b);
    cudaGetSymbolAddress((void**)&z2a, g_z2a); cudaGetSymbolAddress((void**)&z2b, g_z2b);
    cudaGetSymbolAddress((void**)&wca, g_wca); cudaGetSymbolAddress((void**)&wcb, g_wcb);
    cudaGetSymbolAddress((void**)&wla, g_wla); cudaGetSymbolAddress((void**)&wlb, g_wlb);
    cudaGetSymbolAddress((void**)&w2a, g_w2a); cudaGetSymbolAddress((void**)&w2b, g_w2b);
    cudaGetSymbolAddress((void**)&w3a, g_w3a); cudaGetSymbolAddress((void**)&w3b, g_w3b);
    cudaGetSymbolAddress((void**)&z3, g_z3);

    cudaFuncSetAttribute(mgemm<false, true>, cudaFuncAttributeMaxDynamicSharedMemorySize, MG_SMEM);
    cudaFuncSetAttribute(mgemm<true, true>,  cudaFuncAttributeMaxDynamicSharedMemorySize, MG_SMEM);
    cudaFuncSetAttribute(mgemm<true, false>, cudaFuncAttributeMaxDynamicSharedMemorySize, MG_SMEM);

    // setup (cheap, deterministic, in-graph)
    pool1_kernel<<<(D1v * H1v * W1v + 255) / 256, 256>>>(V);
    pool2_kernel<<<(D2v * H2v * W2v + 255) / 256, 256>>>();
    prep_split<<<(128 * 384 + 255) / 256, 256>>>(conv_w, wca, wcb, 128, 375, 384);
    prep_split<<<(128 * 128 + 255) / 256, 256>>>(lfc_w, wla, wlb, 128, 128, 128);
    prep_split<<<(512 * 256 + 255) / 256, 256>>>(fc2_w, w2a, w2b, 512, 256, 256);
    prep_split<<<(256 * 512 + 255) / 256, 256>>>(fc3_w, w3a, w3b, 256, 512, 512);

    const int MB = (M_PTS + 127) / 128;   // 782
    for (int step = 0; step < 5; step++) {
        const float* xcur = (step == 0) ? x_in : xbuf;
        sample_kernel<<<(M_PTS + 7) / 8, 256>>>(xcur, V, fc1_w, fc1_b);
        // zl = v @ conv_w^T + conv_b  (N=128)
        mgemm<false, true><<<dim3(MB, 1), 256, MG_SMEM>>>(
            va, vb, wca, wcb, nullptr, zla, zlb, conv_b, M_PTS, 384, 384, 384, 128);
        // z_local = zl @ lfc_w^T + lfc_b  -> z1 cols [128,256)
        mgemm<false, true><<<dim3(MB, 1), 256, MG_SMEM>>>(
            zla, zlb, wla, wlb, nullptr, z1a + 128, z1b + 128, lfc_b, M_PTS, 128, 128, 128, 256);
        // z2 = leaky(z1 @ fc2_w^T + b2)  (N=512)
        mgemm<true, true><<<dim3(MB, 4), 256, MG_SMEM>>>(
            z1a, z1b, w2a, w2b, nullptr, z2a, z2b, fc2_b, M_PTS, 256, 256, 256, 512);
        // z3 = leaky(z2 @ fc3_w^T + b3)  (N=256, fp32 out)
        mgemm<true, false><<<dim3(MB, 2), 256, MG_SMEM>>>(
            z2a, z2b, w3a, w3b, z3, nullptr, nullptr, fc3_b, M_PTS, 512, 512, 512, 256);
        // x += 0.2 * (z3 @ w4^T + b4)
        fc4_kernel<<<(M_PTS + 255) / 256, 256>>>(xcur, xbuf, fc4_w, fc4_b);
    }
}

// round 17
// speedup vs baseline: 1.3788x; 1.2330x over previous
#include <cuda_runtime.h>
#include <cuda_fp16.h>
#include <cstdint>
#include <cstddef>

#define M_PTS 100000

// level-0 volume dims (D,H,W)
#define D0v 176
#define H0v 208
#define W0v 176
#define D1v 88
#define H1v 104
#define W1v 88
#define D2v 44
#define H2v 52
#define W2v 44

// ================= helpers =================
__device__ __forceinline__ uint32_t smem_to_u32(const void* p) {
    uint32_t a;
    asm("{ .reg .u64 t; cvta.to.shared.u64 t, %1; cvt.u32.u64 %0, t; }" : "=r"(a) : "l"(p));
    return a;
}

// fp16 2-way split with scaled low plane:
//   a ~= h0 + h1/2048,  h0 = f16(a), h1 = f16((a - h0) * 2048)   (residual ~2^-22 |a|)
__device__ __forceinline__ void split2h(float a, __half& h0, __half& h1) {
    h0 = __float2half_rn(a);
    float r = __fadd_rn(a, -__half2float(h0));
    h1 = __float2half_rn(__fmul_rn(r, 2048.0f));
}

__device__ __forceinline__ void ldm4(uint32_t addr, uint32_t& r0, uint32_t& r1, uint32_t& r2, uint32_t& r3) {
    asm volatile("ldmatrix.sync.aligned.m8n8.x4.shared.b16 {%0,%1,%2,%3}, [%4];"
                 : "=r"(r0), "=r"(r1), "=r"(r2), "=r"(r3) : "r"(addr));
}

// D = A*B + 0
__device__ __forceinline__ void mma_f16_zero(float* d, const uint32_t* a, const uint32_t* b) {
    asm volatile(
        "mma.sync.aligned.m16n8k16.row.col.f32.f16.f16.f32 "
        "{%0,%1,%2,%3}, {%4,%5,%6,%7}, {%8,%9}, {%10,%10,%10,%10};\n"
        : "=f"(d[0]), "=f"(d[1]), "=f"(d[2]), "=f"(d[3])
        : "r"(a[0]), "r"(a[1]), "r"(a[2]), "r"(a[3]), "r"(b[0]), "r"(b[1]), "f"(0.0f));
}
// D += A*B
__device__ __forceinline__ void mma_f16_acc(float* d, const uint32_t* a, const uint32_t* b) {
    asm volatile(
        "mma.sync.aligned.m16n8k16.row.col.f32.f16.f16.f32 "
        "{%0,%1,%2,%3}, {%4,%5,%6,%7}, {%8,%9}, {%0,%1,%2,%3};\n"
        : "+f"(d[0]), "+f"(d[1]), "+f"(d[2]), "+f"(d[3])
        : "r"(a[0]), "r"(a[1]), "r"(a[2]), "r"(a[3]), "r"(b[0]), "r"(b[1]));
}

// cp.async 16B (sm_80+ baseline; LDGSTS in SASS). src_size=0 -> zero-fill, no read.
__device__ __forceinline__ void cpa16(uint32_t saddr, const void* gptr, bool valid) {
    int sz = valid ? 16 : 0;
    asm volatile("cp.async.cg.shared.global [%0], [%1], 16, %2;"
                 :: "r"(saddr), "l"(gptr), "r"(sz));
}
#define CP_COMMIT() asm volatile("cp.async.commit_group;" ::: "memory")
#define CP_WAIT1()  asm volatile("cp.async.wait_group 1;" ::: "memory")
#define CP_WAIT0()  asm volatile("cp.async.wait_group 0;" ::: "memory")

// ================= static device scratch =================
__device__ float g_vol1[D1v * H1v * W1v];
__device__ float g_vol2[D2v * H2v * W2v];
// activation split planes (fp16, low plane pre-scaled x2048)
__device__ __half g_va[(size_t)M_PTS * 384], g_vb[(size_t)M_PTS * 384];
__device__ __half g_zla[(size_t)M_PTS * 128], g_zlb[(size_t)M_PTS * 128];
__device__ __half g_z1a[(size_t)M_PTS * 256], g_z1b[(size_t)M_PTS * 256];
__device__ __half g_z2a[(size_t)M_PTS * 512], g_z2b[(size_t)M_PTS * 512];
__device__ float g_z3[(size_t)M_PTS * 256];
// weight split planes (fp16), [n][k] k-major (native layout — no transpose needed)
__device__ __half g_wca[128 * 384], g_wcb[128 * 384];
__device__ __half g_wla[128 * 128], g_wlb[128 * 128];
__device__ __half g_w2a[512 * 256], g_w2b[512 * 256];
__device__ __half g_w3a[256 * 512], g_w3b[256 * 512];

// ================= setup kernels =================
__global__ void pool1_kernel(const float* __restrict__ V) {
    int n = blockIdx.x * blockDim.x + threadIdx.x;
    if (n >= D1v * H1v * W1v) return;
    int xx = n % W1v; int t = n / W1v; int yy = t % H1v; int zz = t / H1v;
    float s = 0.f;
#pragma unroll
    for (int dz = 0; dz < 2; dz++)
#pragma unroll
        for (int dy = 0; dy < 2; dy++)
#pragma unroll
            for (int dx = 0; dx < 2; dx++)
                s = __fadd_rn(s, V[((size_t)(2 * zz + dz) * H0v + (2 * yy + dy)) * W0v + (2 * xx + dx)]);
    g_vol1[n] = __fmul_rn(s, 0.125f);
}

__global__ void pool2_kernel() {
    int n = blockIdx.x * blockDim.x + threadIdx.x;
    if (n >= D2v * H2v * W2v) return;
    int xx = n % W2v; int t = n / W2v; int yy = t % H2v; int zz = t / H2v;
    float s = 0.f;
#pragma unroll
    for (int dz = 0; dz < 2; dz++)
#pragma unroll
        for (int dy = 0; dy < 2; dy++)
#pragma unroll
            for (int dx = 0; dx < 2; dx++)
                s = __fadd_rn(s, g_vol1[((size_t)(2 * zz + dz) * H1v + (2 * yy + dy)) * W1v + (2 * xx + dx)]);
    g_vol2[n] = __fmul_rn(s, 0.125f);
}

// split weight matrix [rows][srcK] into 2 fp16 planes [rows][dstK] (zero-padded)
__global__ void prep_split(const float* __restrict__ src,
                           __half* __restrict__ d0, __half* __restrict__ d1,
                           int rows, int srcK, int dstK) {
    int idx = blockIdx.x * blockDim.x + threadIdx.x;
    if (idx >= rows * dstK) return;
    int r = idx / dstK, k = idx - r * dstK;
    float a = (k < srcK) ? src[r * srcK + k] : 0.f;
    __half h0, h1;
    split2h(a, h0, h1);
    d0[idx] = h0; d1[idx] = h1;
}

// ================= sampling kernel (math UNCHANGED — matches reference bitwise) =================
// Lane->sample permutation: x-shift index (p0) varies fastest across lanes so a
// warp's 8-gather bundle hits adjacent x voxels (1-2 sectors instead of ~25).
// Pure re-assignment of which lane computes which s — identical values/addresses.
__global__ void sample_kernel(const float* __restrict__ x, const float* __restrict__ V,
                              const float* __restrict__ fc1_w, const float* __restrict__ fc1_b) {
    const int NW = 8;
    __shared__ int   s_xi0[NW][5], s_xi1[NW][5];
    __shared__ int   s_yo0[NW][5], s_yo1[NW][5];
    __shared__ int   s_zo0[NW][5], s_zo1[NW][5];
    __shared__ float s_wx[NW][5], s_wy[NW][5], s_wz[NW][5];

    int w = threadIdx.x >> 5, lane = threadIdx.x & 31;
    int m = blockIdx.x * NW + w;
    if (m >= M_PTS) return;

    float x0 = __ldg(&x[3 * m + 0]);
    float x1 = __ldg(&x[3 * m + 1]);
    float x2 = __ldg(&x[3 * m + 2]);
    const float INV_RESC = (float)(208.0 / 176.0);   // == fl32(1/fl32(176/208))

#pragma unroll
    for (int q = 0; q < 3; q++) {
        const float* vol = (q == 0) ? V : (q == 1 ? g_vol1 : g_vol2);
        int Dd = D0v >> q, Hh = H0v >> q, Ww = W0v >> q;

        if (lane < 15) {
            int a = lane / 5, j = lane % 5;
            float xc = (a == 0) ? x0 : (a == 1 ? x1 : x2);
            int dim = (a == 0) ? Ww : (a == 1 ? Hh : Dd);
            float hi = (float)(dim - 1);
            float halfhi = __fmul_rn(0.5f, hi);            // exact
            float g = -3.0f + 1.25f * (float)j;            // exact
            float shift = __fmul_rn(__fmul_rn(__fdiv_rn(g, 208.0f), 2.0f), (float)(1 << q));
            float xq = __fadd_rn(xc, shift);
            float coords = (a == 1) ? xq : __fmul_rn(xq, INV_RESC);  // XLA reciprocal-mul
            float pix = __fmul_rn(__fadd_rn(coords, 1.0f), halfhi);
            pix = fminf(fmaxf(pix, 0.0f), hi);
            float p0f = floorf(pix);
            int i0 = (int)p0f;
            float fr = __fadd_rn(pix, -p0f);
            int i1 = min(i0 + 1, dim - 1);
            if (a == 0)      { s_xi0[w][j] = i0;           s_xi1[w][j] = i1;           s_wx[w][j] = fr; }
            else if (a == 1) { s_yo0[w][j] = i0 * Ww;      s_yo1[w][j] = i1 * Ww;      s_wy[w][j] = fr; }
            else             { s_zo0[w][j] = i0 * Ww * Hh; s_zo1[w][j] = i1 * Ww * Hh; s_wz[w][j] = fr; }
        }
        __syncwarp();

        size_t vbase = (size_t)m * 384 + q * 125;
        for (int t = lane; t < 125; t += 32) {
            // permuted enumeration: p0 (x) fastest across lanes
            int p0 = t % 5, tt = t / 5, p1 = tt % 5, p2 = tt / 5;
            int s = p0 * 25 + p1 * 5 + p2;           // same output slot semantics
            int ix0 = s_xi0[w][p0], ix1 = s_xi1[w][p0];
            float fx = s_wx[w][p0];
            int yo0 = s_yo0[w][p1], yo1 = s_yo1[w][p1];
            float fy = s_wy[w][p1];
            int zo0 = s_zo0[w][p2], zo1 = s_zo1[w][p2];
            float fz = s_wz[w][p2];
            float ox = __fadd_rn(1.0f, -fx);
            float oy = __fadd_rn(1.0f, -fy);
            float oz = __fadd_rn(1.0f, -fz);
            int b00 = zo0 + yo0, b10 = zo0 + yo1, b01 = zo1 + yo0, b11 = zo1 + yo1;
            float v000 = __ldg(vol + b00 + ix0), v100 = __ldg(vol + b00 + ix1);
            float v010 = __ldg(vol + b10 + ix0), v110 = __ldg(vol + b10 + ix1);
            float v001 = __ldg(vol + b01 + ix0), v101 = __ldg(vol + b01 + ix1);
            float v011 = __ldg(vol + b11 + ix0), v111 = __ldg(vol + b11 + ix1);
            float c00 = __fadd_rn(__fmul_rn(v000, ox), __fmul_rn(v100, fx));
            float c10 = __fadd_rn(__fmul_rn(v010, ox), __fmul_rn(v110, fx));
            float c01 = __fadd_rn(__fmul_rn(v001, ox), __fmul_rn(v101, fx));
            float c11 = __fadd_rn(__fmul_rn(v011, ox), __fmul_rn(v111, fx));
            float c0 = __fadd_rn(__fmul_rn(c00, oy), __fmul_rn(c10, fy));
            float c1 = __fadd_rn(__fmul_rn(c01, oy), __fmul_rn(c11, fy));
            float val = __fadd_rn(__fmul_rn(c0, oz), __fmul_rn(c1, fz));
            __half h0, h1;
            split2h(val, h0, h1);
            g_va[vbase + s] = h0; g_vb[vbase + s] = h1;
        }
        __syncwarp();
    }
    if (lane < 9) {
        size_t o = (size_t)m * 384 + 375 + lane;
        g_va[o] = __float2half_rn(0.f);
        g_vb[o] = __float2half_rn(0.f);
    }

    // fc1: z_point = leaky_relu(x @ fc1_w^T + fc1_b)  (unchanged math, split output)
#pragma unroll
    for (int r = 0; r < 4; r++) {
        int o = lane + r * 32;
        float d = __fmul_rn(fc1_w[o * 3 + 0], x0);
        d = fmaf(fc1_w[o * 3 + 1], x1, d);
        d = fmaf(fc1_w[o * 3 + 2], x2, d);
        float z = __fadd_rn(d, fc1_b[o]);
        z = (z >= 0.f) ? z : __fmul_rn(0.2f, z);
        __half h0, h1;
        split2h(z, h0, h1);
        size_t zo = (size_t)m * 256 + o;
        g_z1a[zo] = h0; g_z1b[zo] = h1;
    }
}

// ================= emulated-fp32 GEMM: fp16 3-term split, cp.async double buffer =================
// GRID ORDER: bn = blockIdx.x (fastest), bm = blockIdx.y — CTAs sharing the same
// A-slab run adjacently so A is served from L2 instead of re-streamed from DRAM.
// Compute loop identical to the round-16 kernel (bit-identical numerics).
#define RS 80            // padded smem row stride (32 fp16 + 16B pad) — conflict-free ldmatrix
#define PLANE 10240      // 128 * RS
#define BOFF 20480       // 2 * PLANE (B planes start)
#define HALFBUF 40960    // one stage: A0,A1,B0,B1 planes
#define MG_SMEM 81920    // two stages

template <bool LEAKY, bool SPLITOUT>
__global__ __launch_bounds__(256, 2) void mgemm(
    const __half* __restrict__ A0, const __half* __restrict__ A1,
    const __half* __restrict__ B0, const __half* __restrict__ B1,
    float* __restrict__ Cf,
    __half* __restrict__ C0, __half* __restrict__ C1,
    const float* __restrict__ bias, int M, int K, int lda, int ldb, int ldc) {
    extern __shared__ char smc[];
    uint32_t sb = smem_to_u32(smc);
    int tid = threadIdx.x, lane = tid & 31, wid = tid >> 5;
    int wm = wid & 3, wn = wid >> 2;
    int row0 = blockIdx.y * 128;     // M tile (slow grid dim)
    int col0 = blockIdx.x * 128;     // N tile (fast grid dim -> L2 reuse of A)

    float c[2][8][4];   // master fp32 accumulators
#pragma unroll
    for (int i = 0; i < 2; i++)
#pragma unroll
        for (int j = 0; j < 8; j++)
#pragma unroll
            for (int k = 0; k < 4; k++) c[i][j][k] = 0.f;

    int lrow = tid >> 2, lseg = tid & 3;
    int ti = lane >> 3, rr = lane & 7;
    const float LOWSC = 1.0f / 2048.0f;

    const int nch = K >> 5;

    // ---- async stage of one 32-K chunk into buffer bp ----
    auto stage = [&](int kc, int bp) {
        uint32_t bufo = sb + (uint32_t)bp * HALFBUF;
#pragma unroll
        for (int u = 0; u < 2; u++) {
            int row = lrow + u * 64;
            int gr = row0 + row;
            bool av = (gr < M);
            uint32_t so = bufo + (uint32_t)(row * RS + lseg * 16);
            size_t ga = av ? ((size_t)gr * lda + kc + lseg * 8) : 0;
            cpa16(so, A0 + ga, av);
            cpa16(so + PLANE, A1 + ga, av);
            size_t gb = (size_t)(col0 + row) * ldb + kc + lseg * 8;
            cpa16(so + BOFF, B0 + gb, true);
            cpa16(so + BOFF + PLANE, B1 + gb, true);
        }
    };

    stage(0, 0);
    CP_COMMIT();

    for (int ic = 0; ic < nch; ic++) {
        uint32_t bo = (uint32_t)(ic & 1) * HALFBUF;
        if (ic + 1 < nch) {
            stage((ic + 1) << 5, (ic & 1) ^ 1);
            CP_COMMIT();
            CP_WAIT1();
        } else {
            CP_WAIT0();
        }
        __syncthreads();

        // ---- compute chunk from buffer bo (per-k16 flush, low register pressure) ----
#pragma unroll
        for (int kk = 0; kk < 2; kk++) {
            uint32_t ah[2][4], al[2][4];
#pragma unroll
            for (int mi = 0; mi < 2; mi++) {
                uint32_t abase = sb + bo +
                    (uint32_t)((wm * 32 + mi * 16 + rr + (ti & 1) * 8) * RS + (ti >> 1) * 16 + kk * 32);
                ldm4(abase, ah[mi][0], ah[mi][1], ah[mi][2], ah[mi][3]);
                ldm4(abase + PLANE, al[mi][0], al[mi][1], al[mi][2], al[mi][3]);
            }
#pragma unroll
            for (int jp = 0; jp < 4; jp++) {
                uint32_t bbase = sb + bo + BOFF +
                    (uint32_t)((wn * 64 + (jp * 2 + (ti >> 1)) * 8 + rr) * RS + (ti & 1) * 16 + kk * 32);
                uint32_t bh[2][2], bl[2][2];
                ldm4(bbase, bh[0][0], bh[0][1], bh[1][0], bh[1][1]);
                ldm4(bbase + PLANE, bl[0][0], bl[0][1], bl[1][0], bl[1][1]);
#pragma unroll
                for (int half = 0; half < 2; half++) {
                    int nj = 2 * jp + half;
#pragma unroll
                    for (int mi = 0; mi < 2; mi++) {
                        float dhh[4], dlo[4];
                        mma_f16_zero(dhh, ah[mi], bh[half]);
                        mma_f16_zero(dlo, ah[mi], bl[half]);
                        mma_f16_acc(dlo, al[mi], bh[half]);
#pragma unroll
                        for (int r = 0; r < 4; r++) {
                            float t = __fadd_rn(c[mi][nj][r], dhh[r]);
                            c[mi][nj][r] = fmaf(dlo[r], LOWSC, t);
                        }
                    }
                }
            }
        }
        __syncthreads();
    }

    // ---- epilogue ----
    int g = lane >> 2, i2 = (lane & 3) * 2;
#pragma unroll
    for (int mi = 0; mi < 2; mi++) {
#pragma unroll
        for (int half = 0; half < 2; half++) {
            int gr = row0 + wm * 32 + mi * 16 + g + half * 8;
            if (gr >= M) continue;
#pragma unroll
            for (int nj = 0; nj < 8; nj++) {
                int gc = col0 + wn * 64 + nj * 8 + i2;
                float v0 = __fadd_rn(c[mi][nj][half * 2 + 0], __ldg(&bias[gc]));
                float v1 = __fadd_rn(c[mi][nj][half * 2 + 1], __ldg(&bias[gc + 1]));
                if (LEAKY) {
                    v0 = (v0 >= 0.f) ? v0 : __fmul_rn(0.2f, v0);
                    v1 = (v1 >= 0.f) ? v1 : __fmul_rn(0.2f, v1);
                }
                size_t off = (size_t)gr * ldc + gc;
                if (SPLITOUT) {
                    __half h0, h1, j0, j1;
                    split2h(v0, h0, h1);
                    split2h(v1, j0, j1);
                    *reinterpret_cast<__half2*>(C0 + off) = __halves2half2(h0, j0);
                    *reinterpret_cast<__half2*>(C1 + off) = __halves2half2(h1, j1);
                } else {
                    *reinterpret_cast<float2*>(Cf + off) = make_float2(v0, v1);
                }
            }
        }
    }
}

// ================= fc4 + ODE update (UNCHANGED) =================
__global__ void fc4_kernel(const float* __restrict__ xin, float* __restrict__ xout,
                           const float* __restrict__ w4, const float* __restrict__ b4) {
    int m = blockIdx.x * blockDim.x + threadIdx.x;
    if (m >= M_PTS) return;
    const float* z = &g_z3[(size_t)m * 256];
    float s0 = 0.f, s1 = 0.f, s2 = 0.f;
    for (int k = 0; k < 256; k++) {
        float zv = z[k];
        s0 = fmaf(zv, __ldg(&w4[k]), s0);
        s1 = fmaf(zv, __ldg(&w4[256 + k]), s1);
        s2 = fmaf(zv, __ldg(&w4[512 + k]), s2);
    }
    float d0 = __fadd_rn(s0, b4[0]);
    float d1 = __fadd_rn(s1, b4[1]);
    float d2 = __fadd_rn(s2, b4[2]);
    xout[3 * m + 0] = __fadd_rn(xin[3 * m + 0], __fmul_rn(0.2f, d0));
    xout[3 * m + 1] = __fadd_rn(xin[3 * m + 1], __fmul_rn(0.2f, d1));
    xout[3 * m + 2] = __fadd_rn(xin[3 * m + 2], __fmul_rn(0.2f, d2));
}

// ================= launch =================
extern "C" void kernel_launch(void* const* d_in, const int* in_sizes, int n_in,
                              void* d_out, int out_size) {
    const float* x_in  = (const float*)d_in[0];
    const float* V     = (const float*)d_in[1];
    const float* fc1_w = (const float*)d_in[2];
    const float* fc1_b = (const float*)d_in[3];
    const float* fc2_w = (const float*)d_in[4];
    const float* fc2_b = (const float*)d_in[5];
    const float* fc3_w = (const float*)d_in[6];
    const float* fc3_b = (const float*)d_in[7];
    const float* fc4_w = (const float*)d_in[8];
    const float* fc4_b = (const float*)d_in[9];
    const float* conv_w = (const float*)d_in[10];
    const float* conv_b = (const float*)d_in[11];
    const float* lfc_w  = (const float*)d_in[12];
    const float* lfc_b  = (const float*)d_in[13];
    float* xbuf = (float*)d_out;

    __half *va, *vb, *zla, *zlb, *z1a, *z1b, *z2a, *z2b;
    __half *wca, *wcb, *wla, *wlb, *w2a, *w2b, *w3a, *w3b;
    float* z3;
    cudaGetSymbolAddress((void**)&va, g_va);   cudaGetSymbolAddress((void**)&vb, g_vb);
    cudaGetSymbolAddress((void**)&zla, g_zla); cudaGetSymbolAddress((void**)&zlb, g_zlb);
    cudaGetSymbolAddress((void**)&z1a, g_z1a); cudaGetSymbolAddress((void**)&z1b, g_z1b);
    cudaGetSymbolAddress((void**)&z2a, g_z2a); cudaGetSymbolAddress((void**)&z2b, g_z2b);
    cudaGetSymbolAddress((void**)&wca, g_wca); cudaGetSymbolAddress((void**)&wcb, g_wcb);
    cudaGetSymbolAddress((void**)&wla, g_wla); cudaGetSymbolAddress((void**)&wlb, g_wlb);
    cudaGetSymbolAddress((void**)&w2a, g_w2a); cudaGetSymbolAddress((void**)&w2b, g_w2b);
    cudaGetSymbolAddress((void**)&w3a, g_w3a); cudaGetSymbolAddress((void**)&w3b, g_w3b);
    cudaGetSymbolAddress((void**)&z3, g_z3);

    cudaFuncSetAttribute(mgemm<false, true>, cudaFuncAttributeMaxDynamicSharedMemorySize, MG_SMEM);
    cudaFuncSetAttribute(mgemm<true, true>,  cudaFuncAttributeMaxDynamicSharedMemorySize, MG_SMEM);
    cudaFuncSetAttribute(mgemm<true, false>, cudaFuncAttributeMaxDynamicSharedMemorySize, MG_SMEM);

    // setup (cheap, deterministic, in-graph)
    pool1_kernel<<<(D1v * H1v * W1v + 255) / 256, 256>>>(V);
    pool2_kernel<<<(D2v * H2v * W2v + 255) / 256, 256>>>();
    prep_split<<<(128 * 384 + 255) / 256, 256>>>(conv_w, wca, wcb, 128, 375, 384);
    prep_split<<<(128 * 128 + 255) / 256, 256>>>(lfc_w, wla, wlb, 128, 128, 128);
    prep_split<<<(512 * 256 + 255) / 256, 256>>>(fc2_w, w2a, w2b, 512, 256, 256);
    prep_split<<<(256 * 512 + 255) / 256, 256>>>(fc3_w, w3a, w3b, 256, 512, 512);

    const int MB = (M_PTS + 127) / 128;   // 782
    for (int step = 0; step < 5; step++) {
        const float* xcur = (step == 0) ? x_in : xbuf;
        sample_kernel<<<(M_PTS + 7) / 8, 256>>>(xcur, V, fc1_w, fc1_b);
        // zl = v @ conv_w^T + conv_b  (N=128 -> 1 n-tile)
        mgemm<false, true><<<dim3(1, MB), 256, MG_SMEM>>>(
            va, vb, wca, wcb, nullptr, zla, zlb, conv_b, M_PTS, 384, 384, 384, 128);
        // z_local = zl @ lfc_w^T + lfc_b  -> z1 cols [128,256)
        mgemm<false, true><<<dim3(1, MB), 256, MG_SMEM>>>(
            zla, zlb, wla, wlb, nullptr, z1a + 128, z1b + 128, lfc_b, M_PTS, 128, 128, 128, 256);
        // z2 = leaky(z1 @ fc2_w^T + b2)  (N=512 -> 4 n-tiles, n fastest for L2 A-reuse)
        mgemm<true, true><<<dim3(4, MB), 256, MG_SMEM>>>(
            z1a, z1b, w2a, w2b, nullptr, z2a, z2b, fc2_b, M_PTS, 256, 256, 256, 512);
        // z3 = leaky(z2 @ fc3_w^T + b3)  (N=256 -> 2 n-tiles, fp32 out)
        mgemm<true, false><<<dim3(2, MB), 256, MG_SMEM>>>(
            z2a, z2b, w3a, w3b, z3, nullptr, nullptr, fc3_b, M_PTS, 512, 512, 512, 256);
        // x += 0.2 * (z3 @ w4^T + b4)
        fc4_kernel<<<(M_PTS + 255) / 256, 256>>>(xcur, xbuf, fc4_w, fc4_b);
    }
}